// round 1
// baseline (speedup 1.0000x reference)
#include <cuda_runtime.h>
#include <cuda_bf16.h>

// Problem constants
#define S_LEN 2048
#define BATCH 2
#define EMB   1024
#define HEADS 16
#define HDIM  64
#define MROWS (S_LEN * BATCH)   // 4096

// Scratch (device globals: allocation-free rule)
__device__ float g_q[MROWS * EMB];
__device__ float g_k[MROWS * EMB];
__device__ float g_v[MROWS * EMB];
__device__ float g_ao[MROWS * EMB];

// ---------------------------------------------------------------------------
// GEMM: Y[m][n] = sum_k X[m][k] * W[n][k] + bias[n]
// 128x128 block tile, TILE_K=16, 256 threads, 8x8 per thread, fp32 SIMT.
// ---------------------------------------------------------------------------
__global__ __launch_bounds__(256) void gemm_bias_kernel(
    const float* __restrict__ X, const float* __restrict__ W,
    const float* __restrict__ bias, float* __restrict__ Y,
    int M, int N, int K)
{
    __shared__ __align__(16) float As[16][128];
    __shared__ __align__(16) float Bs[16][128];

    const int t  = threadIdx.x;
    const int m0 = blockIdx.y * 128;
    const int n0 = blockIdx.x * 128;

    const int lr = t >> 2;          // loader row 0..63 (and +64)
    const int lk = (t & 3) << 2;    // loader k offset 0,4,8,12

    const int tx = t & 15;          // col group
    const int ty = t >> 4;          // row group

    float acc[8][8];
    #pragma unroll
    for (int i = 0; i < 8; i++)
        #pragma unroll
        for (int j = 0; j < 8; j++) acc[i][j] = 0.f;

    const float* Xp0 = X + (size_t)(m0 + lr)      * K + lk;
    const float* Xp1 = X + (size_t)(m0 + lr + 64) * K + lk;
    const float* Wp0 = W + (size_t)(n0 + lr)      * K + lk;
    const float* Wp1 = W + (size_t)(n0 + lr + 64) * K + lk;

    for (int k0 = 0; k0 < K; k0 += 16) {
        float4 a0 = *(const float4*)(Xp0 + k0);
        float4 a1 = *(const float4*)(Xp1 + k0);
        float4 b0 = *(const float4*)(Wp0 + k0);
        float4 b1 = *(const float4*)(Wp1 + k0);

        __syncthreads();
        As[lk + 0][lr]      = a0.x; As[lk + 1][lr]      = a0.y;
        As[lk + 2][lr]      = a0.z; As[lk + 3][lr]      = a0.w;
        As[lk + 0][lr + 64] = a1.x; As[lk + 1][lr + 64] = a1.y;
        As[lk + 2][lr + 64] = a1.z; As[lk + 3][lr + 64] = a1.w;
        Bs[lk + 0][lr]      = b0.x; Bs[lk + 1][lr]      = b0.y;
        Bs[lk + 2][lr]      = b0.z; Bs[lk + 3][lr]      = b0.w;
        Bs[lk + 0][lr + 64] = b1.x; Bs[lk + 1][lr + 64] = b1.y;
        Bs[lk + 2][lr + 64] = b1.z; Bs[lk + 3][lr + 64] = b1.w;
        __syncthreads();

        #pragma unroll
        for (int kk = 0; kk < 16; kk++) {
            float a[8], b[8];
            *(float4*)&a[0] = *(const float4*)&As[kk][ty * 8];
            *(float4*)&a[4] = *(const float4*)&As[kk][ty * 8 + 4];
            *(float4*)&b[0] = *(const float4*)&Bs[kk][tx * 8];
            *(float4*)&b[4] = *(const float4*)&Bs[kk][tx * 8 + 4];
            #pragma unroll
            for (int i = 0; i < 8; i++)
                #pragma unroll
                for (int j = 0; j < 8; j++)
                    acc[i][j] += a[i] * b[j];
        }
    }

    float bv[8];
    #pragma unroll
    for (int j = 0; j < 8; j++) bv[j] = bias[n0 + tx * 8 + j];

    #pragma unroll
    for (int i = 0; i < 8; i++) {
        float* yp = Y + (size_t)(m0 + ty * 8 + i) * N + n0 + tx * 8;
        float4 r0, r1;
        r0.x = acc[i][0] + bv[0]; r0.y = acc[i][1] + bv[1];
        r0.z = acc[i][2] + bv[2]; r0.w = acc[i][3] + bv[3];
        r1.x = acc[i][4] + bv[4]; r1.y = acc[i][5] + bv[5];
        r1.z = acc[i][6] + bv[6]; r1.w = acc[i][7] + bv[7];
        *(float4*)(yp)     = r0;
        *(float4*)(yp + 4) = r1;
    }
}

// ---------------------------------------------------------------------------
// Causal flash attention, fp32.
// Q/K/V layouts: linear [m=(s*B+b)][n=h*64+d] (direct output of gemm_bias).
// Block: 64 query rows, 256 threads (4 threads per row, 16 dims each).
// Online softmax (batch-invariant compatible: exp fp32, sum fp32).
// ---------------------------------------------------------------------------
#define BR 64
#define BC 64

__global__ __launch_bounds__(256) void flash_attn_kernel(
    const float* __restrict__ Q, const float* __restrict__ K,
    const float* __restrict__ V, float* __restrict__ O)
{
    const int qt = blockIdx.x;   // 0..31
    const int h  = blockIdx.y;   // 0..15
    const int b  = blockIdx.z;   // 0..1
    const int t  = threadIdx.x;

    const int qr   = t >> 2;     // 0..63 query row within tile
    const int part = t & 3;      // dim slice
    const int d0   = part * 16;
    const int qs   = qt * BR;
    const float scale = 0.125f;  // 1/sqrt(64)

    __shared__ __align__(16) float Ks[BC][HDIM];
    __shared__ __align__(16) float Vs[BC][HDIM];

    float qreg[16];
    {
        const float* qp = Q + ((size_t)(qs + qr) * BATCH + b) * EMB + h * HDIM + d0;
        #pragma unroll
        for (int i = 0; i < 16; i += 4)
            *(float4*)&qreg[i] = *(const float4*)&qp[i];
    }

    float o[16];
    #pragma unroll
    for (int i = 0; i < 16; i++) o[i] = 0.f;
    float m = -1e30f, l = 0.f;

    const int warp_qr_max = qs + ((t >> 5) << 3) + 7;  // max global q row in this warp

    const int nkt = qt + 1;
    for (int kt = 0; kt < nkt; kt++) {
        const int ks = kt * BC;

        // cooperative tile load: 64 rows x 64 dims, each thread 16 floats per tile
        {
            const int j = t >> 2;
            const int c = (t & 3) * 16;
            const float* kp = K + ((size_t)(ks + j) * BATCH + b) * EMB + h * HDIM + c;
            const float* vp = V + ((size_t)(ks + j) * BATCH + b) * EMB + h * HDIM + c;
            float4 kr[4], vr[4];
            #pragma unroll
            for (int i = 0; i < 4; i++) {
                kr[i] = *(const float4*)&kp[i * 4];
                vr[i] = *(const float4*)&vp[i * 4];
            }
            __syncthreads();
            #pragma unroll
            for (int i = 0; i < 4; i++) {
                *(float4*)&Ks[j][c + i * 4] = kr[i];
                *(float4*)&Vs[j][c + i * 4] = vr[i];
            }
            __syncthreads();
        }

        #pragma unroll 1
        for (int c0 = 0; c0 < BC; c0 += 16) {
            // warp-uniform causal skip (safe with shuffles below)
            if (ks + c0 > warp_qr_max) break;

            float p[16];
            float cmax = -1e30f;
            #pragma unroll
            for (int j = 0; j < 16; j++) {
                const int kj = c0 + j;
                float s = 0.f;
                #pragma unroll
                for (int i = 0; i < 16; i++)
                    s += qreg[i] * Ks[kj][d0 + i];
                s += __shfl_xor_sync(0xffffffffu, s, 1);
                s += __shfl_xor_sync(0xffffffffu, s, 2);
                s *= scale;
                if (ks + kj > qs + qr) s = -1e30f;
                p[j] = s;
                cmax = fmaxf(cmax, s);
            }
            const float mnew = fmaxf(m, cmax);
            const float sf   = __expf(m - mnew);
            float psum = 0.f;
            #pragma unroll
            for (int j = 0; j < 16; j++) {
                p[j] = __expf(p[j] - mnew);
                psum += p[j];
            }
            l = l * sf + psum;
            m = mnew;
            #pragma unroll
            for (int i = 0; i < 16; i++) o[i] *= sf;
            #pragma unroll
            for (int j = 0; j < 16; j++) {
                #pragma unroll
                for (int i = 0; i < 16; i++)
                    o[i] += p[j] * Vs[c0 + j][d0 + i];
            }
        }
    }

    const float inv = 1.f / l;
    float* op = O + ((size_t)(qs + qr) * BATCH + b) * EMB + h * HDIM + d0;
    #pragma unroll
    for (int i = 0; i < 16; i++) o[i] *= inv;
    #pragma unroll
    for (int i = 0; i < 16; i += 4)
        *(float4*)&op[i] = *(const float4*)&o[i];
}

// ---------------------------------------------------------------------------
// Launch: q/k/v projections -> flash attention -> output projection
// Input order (metadata): query, key, value, Wq, bq, Wk, bk, Wv, bv, Wo, bo
// ---------------------------------------------------------------------------
extern "C" void kernel_launch(void* const* d_in, const int* in_sizes, int n_in,
                              void* d_out, int out_size)
{
    (void)in_sizes; (void)n_in; (void)out_size;
    const float* query = (const float*)d_in[0];
    const float* key   = (const float*)d_in[1];
    const float* value = (const float*)d_in[2];
    const float* Wq    = (const float*)d_in[3];
    const float* bq    = (const float*)d_in[4];
    const float* Wk    = (const float*)d_in[5];
    const float* bk    = (const float*)d_in[6];
    const float* Wv    = (const float*)d_in[7];
    const float* bv    = (const float*)d_in[8];
    const float* Wo    = (const float*)d_in[9];
    const float* bo    = (const float*)d_in[10];
    float* out = (float*)d_out;

    float *q, *k, *v, *ao;
    cudaGetSymbolAddress((void**)&q,  g_q);
    cudaGetSymbolAddress((void**)&k,  g_k);
    cudaGetSymbolAddress((void**)&v,  g_v);
    cudaGetSymbolAddress((void**)&ao, g_ao);

    dim3 ggrid(EMB / 128, MROWS / 128);   // (8, 32)
    gemm_bias_kernel<<<ggrid, 256>>>(query, Wq, bq, q,  MROWS, EMB, EMB);
    gemm_bias_kernel<<<ggrid, 256>>>(key,   Wk, bk, k,  MROWS, EMB, EMB);
    gemm_bias_kernel<<<ggrid, 256>>>(value, Wv, bv, v,  MROWS, EMB, EMB);

    dim3 agrid(S_LEN / BR, HEADS, BATCH); // (32, 16, 2)
    flash_attn_kernel<<<agrid, 256>>>(q, k, v, ao);

    gemm_bias_kernel<<<ggrid, 256>>>(ao, Wo, bo, out, MROWS, EMB, EMB);
}

// round 3
// speedup vs baseline: 2.5142x; 2.5142x over previous
#include <cuda_runtime.h>
#include <cuda_bf16.h>
#include <cstdint>

// ---------------------------------------------------------------------------
// Problem constants
// ---------------------------------------------------------------------------
#define S_LEN 2048
#define BATCH 2
#define EMB   1024
#define HEADS 16
#define HDIM  64
#define MROWS (S_LEN * BATCH)      // 4096
#define K3    3072                 // 3 * EMB (bf16x3 split concat along K)

// ---------------------------------------------------------------------------
// Device scratch (allocation-free rule: __device__ globals)
// ---------------------------------------------------------------------------
__device__ float g_q [MROWS * EMB];
__device__ float g_k [MROWS * EMB];
__device__ float g_v [MROWS * EMB];
__device__ float g_ao[MROWS * EMB];

// bf16 split buffers: Xs[m][0:1024]=hi, [1024:2048]=lo, [2048:3072]=hi
//                     Ws[n][0:1024]=hi, [1024:2048]=hi, [2048:3072]=lo
__device__ __align__(128) __nv_bfloat16 g_xs[MROWS * K3];   // 24 MB
__device__ __align__(128) __nv_bfloat16 g_ws[EMB * K3];     //  6 MB

// ---------------------------------------------------------------------------
// PTX helpers (baseline sm_80+ features only; no tcgen05 — harness compiles
// through PTX .target sm_103 which rejects 'a'-suffix features)
// ---------------------------------------------------------------------------
__device__ __forceinline__ uint32_t smem_to_u32(const void* p) {
    uint32_t a;
    asm("{ .reg .u64 t; cvta.to.shared.u64 t, %1; cvt.u32.u64 %0, t; }"
        : "=r"(a) : "l"(p));
    return a;
}

__device__ __forceinline__ void cp_async16(uint32_t s, const void* g) {
    asm volatile("cp.async.cg.shared.global [%0], [%1], 16;"
                 :: "r"(s), "l"(g) : "memory");
}
#define CP_COMMIT() asm volatile("cp.async.commit_group;" ::: "memory")
#define CP_WAIT(n)  asm volatile("cp.async.wait_group %0;" :: "n"(n) : "memory")

__device__ __forceinline__ void ldsm_x4(uint32_t* r, uint32_t addr) {
    asm volatile("ldmatrix.sync.aligned.m8n8.x4.shared.b16 {%0,%1,%2,%3}, [%4];"
        : "=r"(r[0]), "=r"(r[1]), "=r"(r[2]), "=r"(r[3]) : "r"(addr));
}
__device__ __forceinline__ void ldsm_x2(uint32_t* r, uint32_t addr) {
    asm volatile("ldmatrix.sync.aligned.m8n8.x2.shared.b16 {%0,%1}, [%2];"
        : "=r"(r[0]), "=r"(r[1]) : "r"(addr));
}

__device__ __forceinline__ void mma_bf16(float* d, const uint32_t* a, const uint32_t* b) {
    asm volatile(
        "mma.sync.aligned.m16n8k16.row.col.f32.bf16.bf16.f32 "
        "{%0,%1,%2,%3}, {%4,%5,%6,%7}, {%8,%9}, {%0,%1,%2,%3};"
        : "+f"(d[0]), "+f"(d[1]), "+f"(d[2]), "+f"(d[3])
        : "r"(a[0]), "r"(a[1]), "r"(a[2]), "r"(a[3]), "r"(b[0]), "r"(b[1]));
}

// ---------------------------------------------------------------------------
// Split kernel: fp32 [rows,1024] -> bf16 [rows,3072]
// mode 0 (activations): segments hi | lo | hi
// mode 1 (weights):     segments hi | hi | lo
// Thread handles 8 consecutive fp32 elements.
// ---------------------------------------------------------------------------
struct alignas(16) bf16x8 { __nv_bfloat16 v[8]; };

__global__ __launch_bounds__(256) void split3_kernel(
    const float* __restrict__ X, __nv_bfloat16* __restrict__ out, int mode)
{
    const uint32_t t = blockIdx.x * 256u + threadIdx.x;
    const uint32_t e = t * 8u;
    const uint32_t m = e >> 10, k = e & 1023u;

    float x[8];
    *(float4*)&x[0] = *(const float4*)(X + e);
    *(float4*)&x[4] = *(const float4*)(X + e + 4);

    bf16x8 H, L;
    #pragma unroll
    for (int i = 0; i < 8; i++) {
        __nv_bfloat16 h = __float2bfloat16(x[i]);
        H.v[i] = h;
        L.v[i] = __float2bfloat16(x[i] - __bfloat162float(h));
    }

    __nv_bfloat16* rb = out + (size_t)m * K3 + k;
    if (mode == 0) {            // hi | lo | hi
        *(bf16x8*)(rb)        = H;
        *(bf16x8*)(rb + 1024) = L;
        *(bf16x8*)(rb + 2048) = H;
    } else {                    // hi | hi | lo
        *(bf16x8*)(rb)        = H;
        *(bf16x8*)(rb + 1024) = H;
        *(bf16x8*)(rb + 2048) = L;
    }
}

// ---------------------------------------------------------------------------
// bf16 mma.sync GEMM: Y[4096,1024] = Xs[4096,3072] · Ws[1024,3072]^T + bias
// CTA tile 128x128, BK=32, 256 threads (8 warps, warp tile 64x32),
// double-buffered cp.async, XOR-swizzled smem, fp32 accum, fused bias.
// ---------------------------------------------------------------------------
#define BM 128
#define BN 128
#define BK 32
#define NKT (K3 / BK)          // 96
#define STAGE 16384            // A 8KB + B 8KB

__global__ __launch_bounds__(256) void gemm_mma_kernel(
    const __nv_bfloat16* __restrict__ A,   // [MROWS][K3]
    const __nv_bfloat16* __restrict__ B,   // [EMB][K3]
    const float* __restrict__ bias, float* __restrict__ Y)
{
    __shared__ __align__(128) char smem[2 * STAGE];
    const uint32_t sb = smem_to_u32(smem);
    const int tid  = threadIdx.x;
    const int lane = tid & 31, wid = tid >> 5;
    const int bn = blockIdx.x, bm = blockIdx.y;
    const int wm = (wid >> 2) * 64;        // 0 / 64
    const int wn = (wid & 3) * 32;         // 0 / 32 / 64 / 96

    float acc[4][4][4];
    #pragma unroll
    for (int i = 0; i < 4; i++)
        #pragma unroll
        for (int j = 0; j < 4; j++)
            #pragma unroll
            for (int r = 0; r < 4; r++) acc[i][j][r] = 0.f;

    const __nv_bfloat16* Ab = A + (size_t)bm * BM * K3;
    const __nv_bfloat16* Bb = B + (size_t)bn * BN * K3;

    // loader: idx -> (row, 16B-chunk); swizzled store col = c ^ ((r>>1)&3)
    const int r0 = tid >> 2, c0 = tid & 3;
    const uint32_t sa0 = (uint32_t)(r0 * 64 + ((c0 ^ ((r0 >> 1) & 3)) << 4));
    const int r1 = (tid + 256) >> 2, c1 = tid & 3;
    const uint32_t sa1 = (uint32_t)(r1 * 64 + ((c1 ^ ((r1 >> 1) & 3)) << 4));

    #define LOAD_TILE(kt, buf) do {                                          \
        const uint32_t st = sb + (buf) * STAGE;                              \
        const size_t kb = (size_t)(kt) * BK;                                 \
        cp_async16(st + sa0,        Ab + (size_t)r0 * K3 + kb + c0 * 8);     \
        cp_async16(st + sa1,        Ab + (size_t)r1 * K3 + kb + c1 * 8);     \
        cp_async16(st + 8192 + sa0, Bb + (size_t)r0 * K3 + kb + c0 * 8);     \
        cp_async16(st + 8192 + sa1, Bb + (size_t)r1 * K3 + kb + c1 * 8);     \
        CP_COMMIT();                                                         \
    } while (0)

    LOAD_TILE(0, 0);

    for (int kt = 0; kt < NKT; kt++) {
        const int buf = kt & 1;
        if (kt + 1 < NKT) {
            LOAD_TILE(kt + 1, buf ^ 1);
            CP_WAIT(1);
        } else {
            CP_WAIT(0);
        }
        __syncthreads();

        const uint32_t st = sb + buf * STAGE;
        #pragma unroll
        for (int s = 0; s < 2; s++) {          // two k16 steps per BK=32
            uint32_t af[4][4], bf[4][2];
            #pragma unroll
            for (int i = 0; i < 4; i++) {
                const int row = wm + i * 16 + (lane & 7) + (lane & 8);
                const int ch  = s * 2 + (lane >> 4);
                ldsm_x4(af[i], st + row * 64 + ((ch ^ ((row >> 1) & 3)) << 4));
            }
            #pragma unroll
            for (int j = 0; j < 4; j++) {
                const int row = wn + j * 8 + (lane & 7);
                const int ch  = s * 2 + ((lane >> 3) & 1);
                ldsm_x2(bf[j], st + 8192 + row * 64 + ((ch ^ ((row >> 1) & 3)) << 4));
            }
            #pragma unroll
            for (int i = 0; i < 4; i++)
                #pragma unroll
                for (int j = 0; j < 4; j++)
                    mma_bf16(acc[i][j], af[i], bf[j]);
        }
        __syncthreads();
    }
    #undef LOAD_TILE

    // epilogue: fused bias, direct stores
    #pragma unroll
    for (int j = 0; j < 4; j++) {
        const int col = bn * BN + wn + j * 8 + (lane & 3) * 2;
        const float b0 = bias[col], b1 = bias[col + 1];
        #pragma unroll
        for (int i = 0; i < 4; i++) {
            const int row = bm * BM + wm + i * 16 + (lane >> 2);
            float2 v0 = { acc[i][j][0] + b0, acc[i][j][1] + b1 };
            float2 v1 = { acc[i][j][2] + b0, acc[i][j][3] + b1 };
            *(float2*)(Y + (size_t)row * EMB + col)       = v0;
            *(float2*)(Y + (size_t)(row + 8) * EMB + col) = v1;
        }
    }
}

// ---------------------------------------------------------------------------
// Causal flash attention fp32: 1 thread = 1 query row (64 dims in regs).
// 128 rows/block, 128 threads. K/V tiles 64x64 in smem (broadcast LDS reads).
// Heavy (late) q-tiles launch first for better wave balance.
// ---------------------------------------------------------------------------
#define FBR 128
#define FBC 64

__global__ __launch_bounds__(128) void flash_attn_kernel(
    const float* __restrict__ Q, const float* __restrict__ K,
    const float* __restrict__ V, float* __restrict__ O)
{
    const int qt = (gridDim.x - 1) - blockIdx.x;   // reversed: heavy tiles first
    const int h  = blockIdx.y;
    const int b  = blockIdx.z;
    const int tid = threadIdx.x;
    const int qs = qt * FBR;
    const int qrow = qs + tid;
    const float scale = 0.125f;

    __shared__ __align__(16) float Ks[FBC][HDIM];
    __shared__ __align__(16) float Vs[FBC][HDIM];

    float q[64], o[64];
    {
        const float* qp = Q + ((size_t)qrow * BATCH + b) * EMB + h * HDIM;
        #pragma unroll
        for (int d = 0; d < 64; d += 4)
            *(float4*)&q[d] = *(const float4*)&qp[d];
    }
    #pragma unroll
    for (int d = 0; d < 64; d++) o[d] = 0.f;
    float m = -1e30f, l = 0.f;

    const int warp_max = qs + ((tid >> 5) << 5) + 31;
    const int nkt = 2 * qt + 2;

    const int lrow = tid >> 1;
    const int lcol = (tid & 1) * 32;

    for (int kt = 0; kt < nkt; kt++) {
        const int ks = kt * FBC;

        {   // cooperative K/V tile load
            const float* kp = K + ((size_t)(ks + lrow) * BATCH + b) * EMB + h * HDIM + lcol;
            const float* vp = V + ((size_t)(ks + lrow) * BATCH + b) * EMB + h * HDIM + lcol;
            float4 kr[8], vr[8];
            #pragma unroll
            for (int i = 0; i < 8; i++) {
                kr[i] = *(const float4*)&kp[i * 4];
                vr[i] = *(const float4*)&vp[i * 4];
            }
            __syncthreads();
            #pragma unroll
            for (int i = 0; i < 8; i++) {
                *(float4*)&Ks[lrow][lcol + i * 4] = kr[i];
                *(float4*)&Vs[lrow][lcol + i * 4] = vr[i];
            }
            __syncthreads();
        }

        #pragma unroll 1
        for (int c0 = 0; c0 < FBC; c0 += 16) {
            if (ks + c0 > warp_max) break;   // warp-uniform causal skip

            float p[16];
            float cmax = -1e30f;
            #pragma unroll 4
            for (int j = 0; j < 16; j++) {
                const float* kr = &Ks[c0 + j][0];
                float s0 = 0.f, s1 = 0.f, s2 = 0.f, s3 = 0.f;
                #pragma unroll
                for (int d = 0; d < 64; d += 4) {
                    s0 += q[d + 0] * kr[d + 0];
                    s1 += q[d + 1] * kr[d + 1];
                    s2 += q[d + 2] * kr[d + 2];
                    s3 += q[d + 3] * kr[d + 3];
                }
                float s = ((s0 + s1) + (s2 + s3)) * scale;
                if (ks + c0 + j > qrow) s = -1e30f;
                p[j] = s;
                cmax = fmaxf(cmax, s);
            }

            const float mnew = fmaxf(m, cmax);
            const float sf = __expf(m - mnew);
            float psum = 0.f;
            #pragma unroll
            for (int j = 0; j < 16; j++) {
                p[j] = __expf(p[j] - mnew);
                psum += p[j];
            }
            l = l * sf + psum;
            m = mnew;
            #pragma unroll
            for (int d = 0; d < 64; d++) o[d] *= sf;

            #pragma unroll 2
            for (int j = 0; j < 16; j++) {
                const float pj = p[j];
                const float* vr = &Vs[c0 + j][0];
                #pragma unroll
                for (int d = 0; d < 64; d++) o[d] += pj * vr[d];
            }
        }
    }

    const float inv = 1.f / l;
    float* op = O + ((size_t)qrow * BATCH + b) * EMB + h * HDIM;
    #pragma unroll
    for (int d = 0; d < 64; d++) o[d] *= inv;
    #pragma unroll
    for (int d = 0; d < 64; d += 4)
        *(float4*)&op[d] = *(const float4*)&o[d];
}

// ---------------------------------------------------------------------------
// Launch
// Inputs: query, key, value, Wq, bq, Wk, bk, Wv, bv, Wo, bo
// ---------------------------------------------------------------------------
extern "C" void kernel_launch(void* const* d_in, const int* in_sizes, int n_in,
                              void* d_out, int out_size)
{
    (void)in_sizes; (void)n_in; (void)out_size;
    const float* query = (const float*)d_in[0];
    const float* key   = (const float*)d_in[1];
    const float* value = (const float*)d_in[2];
    const float* Wq    = (const float*)d_in[3];
    const float* bq    = (const float*)d_in[4];
    const float* Wk    = (const float*)d_in[5];
    const float* bk    = (const float*)d_in[6];
    const float* Wv    = (const float*)d_in[7];
    const float* bv    = (const float*)d_in[8];
    const float* Wo    = (const float*)d_in[9];
    const float* bo    = (const float*)d_in[10];
    float* out = (float*)d_out;

    float *q, *k, *v, *ao;
    __nv_bfloat16 *xs, *ws;
    cudaGetSymbolAddress((void**)&q,  g_q);
    cudaGetSymbolAddress((void**)&k,  g_k);
    cudaGetSymbolAddress((void**)&v,  g_v);
    cudaGetSymbolAddress((void**)&ao, g_ao);
    cudaGetSymbolAddress((void**)&xs, g_xs);
    cudaGetSymbolAddress((void**)&ws, g_ws);

    const int gsx = MROWS * EMB / (8 * 256);   // 2048 blocks
    const int gsw = EMB * EMB / (8 * 256);     //  512 blocks
    dim3 ggrid(EMB / BN, MROWS / BM);          // (8, 32)

    split3_kernel<<<gsx, 256>>>(query, xs, 0);
    split3_kernel<<<gsw, 256>>>(Wq, ws, 1);
    gemm_mma_kernel<<<ggrid, 256>>>(xs, ws, bq, q);

    split3_kernel<<<gsx, 256>>>(key, xs, 0);
    split3_kernel<<<gsw, 256>>>(Wk, ws, 1);
    gemm_mma_kernel<<<ggrid, 256>>>(xs, ws, bk, k);

    split3_kernel<<<gsx, 256>>>(value, xs, 0);
    split3_kernel<<<gsw, 256>>>(Wv, ws, 1);
    gemm_mma_kernel<<<ggrid, 256>>>(xs, ws, bv, v);

    dim3 agrid(S_LEN / FBR, HEADS, BATCH);     // (16, 16, 2)
    flash_attn_kernel<<<agrid, 128>>>(q, k, v, ao);

    split3_kernel<<<gsx, 256>>>(ao, xs, 0);
    split3_kernel<<<gsw, 256>>>(Wo, ws, 1);
    gemm_mma_kernel<<<ggrid, 256>>>(xs, ws, bo, out);
}

// round 4
// speedup vs baseline: 5.2154x; 2.0744x over previous
#include <cuda_runtime.h>
#include <cuda_bf16.h>
#include <cstdint>

// ---------------------------------------------------------------------------
// Problem constants
// ---------------------------------------------------------------------------
#define S_LEN 2048
#define BATCH 2
#define EMB   1024
#define HEADS 16
#define HDIM  64
#define MROWS (S_LEN * BATCH)      // 4096
#define K3    3072                 // 3 * EMB (bf16x3 split concat along K)

// ---------------------------------------------------------------------------
// Device scratch (allocation-free rule: __device__ globals)
// ---------------------------------------------------------------------------
__device__ float g_q [MROWS * EMB];
__device__ float g_k [MROWS * EMB];
__device__ float g_v [MROWS * EMB];
__device__ float g_ao[MROWS * EMB];

__device__ __align__(128) __nv_bfloat16 g_xs[MROWS * K3];   // 24 MB
__device__ __align__(128) __nv_bfloat16 g_ws[EMB * K3];     //  6 MB

// ---------------------------------------------------------------------------
// PTX helpers (baseline sm_80+ features only — harness lowers via .target
// sm_103 which rejects tcgen05 / 'a'-suffix features)
// ---------------------------------------------------------------------------
__device__ __forceinline__ uint32_t smem_to_u32(const void* p) {
    uint32_t a;
    asm("{ .reg .u64 t; cvta.to.shared.u64 t, %1; cvt.u32.u64 %0, t; }"
        : "=r"(a) : "l"(p));
    return a;
}

__device__ __forceinline__ void cp_async16(uint32_t s, const void* g) {
    asm volatile("cp.async.cg.shared.global [%0], [%1], 16;"
                 :: "r"(s), "l"(g) : "memory");
}
#define CP_COMMIT() asm volatile("cp.async.commit_group;" ::: "memory")
#define CP_WAIT(n)  asm volatile("cp.async.wait_group %0;" :: "n"(n) : "memory")

__device__ __forceinline__ void ldsm_x4(uint32_t* r, uint32_t addr) {
    asm volatile("ldmatrix.sync.aligned.m8n8.x4.shared.b16 {%0,%1,%2,%3}, [%4];"
        : "=r"(r[0]), "=r"(r[1]), "=r"(r[2]), "=r"(r[3]) : "r"(addr));
}
__device__ __forceinline__ void ldsm_x2(uint32_t* r, uint32_t addr) {
    asm volatile("ldmatrix.sync.aligned.m8n8.x2.shared.b16 {%0,%1}, [%2];"
        : "=r"(r[0]), "=r"(r[1]) : "r"(addr));
}

__device__ __forceinline__ void mma_bf16(float* d, const uint32_t* a, const uint32_t* b) {
    asm volatile(
        "mma.sync.aligned.m16n8k16.row.col.f32.bf16.bf16.f32 "
        "{%0,%1,%2,%3}, {%4,%5,%6,%7}, {%8,%9}, {%0,%1,%2,%3};"
        : "+f"(d[0]), "+f"(d[1]), "+f"(d[2]), "+f"(d[3])
        : "r"(a[0]), "r"(a[1]), "r"(a[2]), "r"(a[3]), "r"(b[0]), "r"(b[1]));
}

__device__ __forceinline__ uint32_t pack_bf2(__nv_bfloat16 a, __nv_bfloat16 b) {
    __nv_bfloat162 t; t.x = a; t.y = b;
    return *(uint32_t*)&t;
}

struct alignas(16) bf16x8 { __nv_bfloat16 v[8]; };

// ---------------------------------------------------------------------------
// Split kernel: fp32 [rows,1024] -> bf16 [rows,3072]
// mode 0 (activations): hi | lo | hi ; mode 1 (weights): hi | hi | lo
// ---------------------------------------------------------------------------
__global__ __launch_bounds__(256) void split3_kernel(
    const float* __restrict__ X, __nv_bfloat16* __restrict__ out, int mode)
{
    const uint32_t t = blockIdx.x * 256u + threadIdx.x;
    const uint32_t e = t * 8u;
    const uint32_t m = e >> 10, k = e & 1023u;

    float x[8];
    *(float4*)&x[0] = *(const float4*)(X + e);
    *(float4*)&x[4] = *(const float4*)(X + e + 4);

    bf16x8 H, L;
    #pragma unroll
    for (int i = 0; i < 8; i++) {
        __nv_bfloat16 h = __float2bfloat16(x[i]);
        H.v[i] = h;
        L.v[i] = __float2bfloat16(x[i] - __bfloat162float(h));
    }

    __nv_bfloat16* rb = out + (size_t)m * K3 + k;
    if (mode == 0) {
        *(bf16x8*)(rb)        = H;
        *(bf16x8*)(rb + 1024) = L;
        *(bf16x8*)(rb + 2048) = H;
    } else {
        *(bf16x8*)(rb)        = H;
        *(bf16x8*)(rb + 1024) = H;
        *(bf16x8*)(rb + 2048) = L;
    }
}

// ---------------------------------------------------------------------------
// bf16 mma.sync GEMM (unchanged from round 3 — validated)
// ---------------------------------------------------------------------------
#define BM 128
#define BN 128
#define BK 32
#define NKT (K3 / BK)
#define STAGE 16384

__global__ __launch_bounds__(256) void gemm_mma_kernel(
    const __nv_bfloat16* __restrict__ A,
    const __nv_bfloat16* __restrict__ B,
    const float* __restrict__ bias, float* __restrict__ Y)
{
    __shared__ __align__(128) char smem[2 * STAGE];
    const uint32_t sb = smem_to_u32(smem);
    const int tid  = threadIdx.x;
    const int lane = tid & 31, wid = tid >> 5;
    const int bn = blockIdx.x, bm = blockIdx.y;
    const int wm = (wid >> 2) * 64;
    const int wn = (wid & 3) * 32;

    float acc[4][4][4];
    #pragma unroll
    for (int i = 0; i < 4; i++)
        #pragma unroll
        for (int j = 0; j < 4; j++)
            #pragma unroll
            for (int r = 0; r < 4; r++) acc[i][j][r] = 0.f;

    const __nv_bfloat16* Ab = A + (size_t)bm * BM * K3;
    const __nv_bfloat16* Bb = B + (size_t)bn * BN * K3;

    const int r0 = tid >> 2, c0 = tid & 3;
    const uint32_t sa0 = (uint32_t)(r0 * 64 + ((c0 ^ ((r0 >> 1) & 3)) << 4));
    const int r1 = (tid + 256) >> 2, c1 = tid & 3;
    const uint32_t sa1 = (uint32_t)(r1 * 64 + ((c1 ^ ((r1 >> 1) & 3)) << 4));

    #define LOAD_TILE(kt, buf) do {                                          \
        const uint32_t st = sb + (buf) * STAGE;                              \
        const size_t kb = (size_t)(kt) * BK;                                 \
        cp_async16(st + sa0,        Ab + (size_t)r0 * K3 + kb + c0 * 8);     \
        cp_async16(st + sa1,        Ab + (size_t)r1 * K3 + kb + c1 * 8);     \
        cp_async16(st + 8192 + sa0, Bb + (size_t)r0 * K3 + kb + c0 * 8);     \
        cp_async16(st + 8192 + sa1, Bb + (size_t)r1 * K3 + kb + c1 * 8);     \
        CP_COMMIT();                                                         \
    } while (0)

    LOAD_TILE(0, 0);

    for (int kt = 0; kt < NKT; kt++) {
        const int buf = kt & 1;
        if (kt + 1 < NKT) {
            LOAD_TILE(kt + 1, buf ^ 1);
            CP_WAIT(1);
        } else {
            CP_WAIT(0);
        }
        __syncthreads();

        const uint32_t st = sb + buf * STAGE;
        #pragma unroll
        for (int s = 0; s < 2; s++) {
            uint32_t af[4][4], bf[4][2];
            #pragma unroll
            for (int i = 0; i < 4; i++) {
                const int row = wm + i * 16 + (lane & 7) + (lane & 8);
                const int ch  = s * 2 + (lane >> 4);
                ldsm_x4(af[i], st + row * 64 + ((ch ^ ((row >> 1) & 3)) << 4));
            }
            #pragma unroll
            for (int j = 0; j < 4; j++) {
                const int row = wn + j * 8 + (lane & 7);
                const int ch  = s * 2 + ((lane >> 3) & 1);
                ldsm_x2(bf[j], st + 8192 + row * 64 + ((ch ^ ((row >> 1) & 3)) << 4));
            }
            #pragma unroll
            for (int i = 0; i < 4; i++)
                #pragma unroll
                for (int j = 0; j < 4; j++)
                    mma_bf16(acc[i][j], af[i], bf[j]);
        }
        __syncthreads();
    }
    #undef LOAD_TILE

    #pragma unroll
    for (int j = 0; j < 4; j++) {
        const int col = bn * BN + wn + j * 8 + (lane & 3) * 2;
        const float b0 = bias[col], b1 = bias[col + 1];
        #pragma unroll
        for (int i = 0; i < 4; i++) {
            const int row = bm * BM + wm + i * 16 + (lane >> 2);
            float2 v0 = { acc[i][j][0] + b0, acc[i][j][1] + b1 };
            float2 v1 = { acc[i][j][2] + b0, acc[i][j][3] + b1 };
            *(float2*)(Y + (size_t)row * EMB + col)       = v0;
            *(float2*)(Y + (size_t)(row + 8) * EMB + col) = v1;
        }
    }
}

// ---------------------------------------------------------------------------
// Tensor-core causal flash attention (FA2-style, bf16x3 splits, fp32 softmax).
// Block: 128 q rows x (head, batch); 4 warps, 32 rows each.
// Key tile: 64. QK^T: Qhi·Khi + Qlo·Khi + Qhi·Klo. PV: Phi·Vhi + Plo·Vhi + Phi·Vlo.
// Smem: Qhi/Qlo [128][64], Khi/Klo [64][64], VhiT/VloT [64 dims][64 keys],
// all bf16, 128B rows, XOR-swizzled (ch ^= row&7). 64KB dynamic smem.
// ---------------------------------------------------------------------------
#define FQ 128
#define FK 64
#define OFF_QHI 0
#define OFF_QLO 16384
#define OFF_KHI 32768
#define OFF_KLO 40960
#define OFF_VHI 49152
#define OFF_VLO 57344
#define FLASH_SMEM 65536

__device__ __forceinline__ uint32_t swz(uint32_t base, int row, int ch) {
    return base + (uint32_t)(row * 128) + (uint32_t)(((ch ^ (row & 7)) & 7) << 4);
}

__global__ __launch_bounds__(128, 1) void flash_tc_kernel(
    const float* __restrict__ Q, const float* __restrict__ K,
    const float* __restrict__ V, float* __restrict__ O)
{
    extern __shared__ __align__(128) char fsm[];
    const uint32_t sb = smem_to_u32(fsm);

    const int qt = (int)(gridDim.x - 1) - (int)blockIdx.x;  // heavy tiles first
    const int hh = blockIdx.y;
    const int b  = blockIdx.z;
    const int tid = threadIdx.x, lane = tid & 31, w = tid >> 5;
    const int qs = qt * FQ;
    const float scale = 0.125f;

    // ---- Q convert: thread t -> q row t, 64 dims -> hi/lo smem ----
    {
        const float* qp = Q + ((size_t)(qs + tid) * BATCH + b) * EMB + hh * HDIM;
        float x[64];
        #pragma unroll
        for (int d = 0; d < 64; d += 4)
            *(float4*)&x[d] = *(const float4*)&qp[d];
        #pragma unroll
        for (int c = 0; c < 8; c++) {
            bf16x8 H, L;
            #pragma unroll
            for (int e = 0; e < 8; e++) {
                float vv = x[c * 8 + e];
                __nv_bfloat16 hb = __float2bfloat16(vv);
                H.v[e] = hb;
                L.v[e] = __float2bfloat16(vv - __bfloat162float(hb));
            }
            const uint32_t off = (uint32_t)(tid * 128 + ((c ^ (tid & 7)) << 4));
            *(bf16x8*)(fsm + OFF_QHI + off) = H;
            *(bf16x8*)(fsm + OFF_QLO + off) = L;
        }
    }

    float o[2][8][4];
    #pragma unroll
    for (int i = 0; i < 2; i++)
        #pragma unroll
        for (int j = 0; j < 8; j++)
            #pragma unroll
            for (int r = 0; r < 4; r++) o[i][j][r] = 0.f;
    float mrow[4] = {-1e30f, -1e30f, -1e30f, -1e30f};
    float lrow[4] = {0.f, 0.f, 0.f, 0.f};

    const int wmin = qs + w * 32;
    const int wmax = wmin + 31;
    const int nkt = 2 * qt + 2;

    for (int kt = 0; kt < nkt; kt++) {
        const int ks = kt * FK;
        __syncthreads();   // previous-iteration smem reads done

        // ---- K tile convert: thread -> key (tid>>1), dim-half (tid&1)*32 ----
        {
            const int j = tid >> 1, half = tid & 1, d0 = half * 32;
            const float* kp = K + ((size_t)(ks + j) * BATCH + b) * EMB + hh * HDIM + d0;
            float x[32];
            #pragma unroll
            for (int d = 0; d < 32; d += 4)
                *(float4*)&x[d] = *(const float4*)&kp[d];
            #pragma unroll
            for (int c = 0; c < 4; c++) {
                bf16x8 H, L;
                #pragma unroll
                for (int e = 0; e < 8; e++) {
                    float vv = x[c * 8 + e];
                    __nv_bfloat16 hb = __float2bfloat16(vv);
                    H.v[e] = hb;
                    L.v[e] = __float2bfloat16(vv - __bfloat162float(hb));
                }
                const int ch = half * 4 + c;
                const uint32_t off = (uint32_t)(j * 128 + ((ch ^ (j & 7)) << 4));
                *(bf16x8*)(fsm + OFF_KHI + off) = H;
                *(bf16x8*)(fsm + OFF_KLO + off) = L;
            }
        }
        // ---- V tile convert+transpose: thread -> key pair (tid&31), dims (tid>>5)*16 ----
        {
            const int kp2 = tid & 31, dw = tid >> 5;
            const int jA = 2 * kp2, d0 = dw * 16;
            const float* vA = V + ((size_t)(ks + jA) * BATCH + b) * EMB + hh * HDIM + d0;
            const float* vB = vA + (size_t)BATCH * EMB;
            float xa[16], xb[16];
            #pragma unroll
            for (int d = 0; d < 16; d += 4) {
                *(float4*)&xa[d] = *(const float4*)&vA[d];
                *(float4*)&xb[d] = *(const float4*)&vB[d];
            }
            const int chk = jA >> 3;
            const int boff = 2 * (jA & 7);
            #pragma unroll
            for (int d = 0; d < 16; d++) {
                const int dim = d0 + d;
                __nv_bfloat16 ha = __float2bfloat16(xa[d]);
                __nv_bfloat16 hb = __float2bfloat16(xb[d]);
                __nv_bfloat16 la = __float2bfloat16(xa[d] - __bfloat162float(ha));
                __nv_bfloat16 lb = __float2bfloat16(xb[d] - __bfloat162float(hb));
                const uint32_t off = (uint32_t)(dim * 128 + ((chk ^ (dim & 7)) << 4) + boff);
                *(uint32_t*)(fsm + OFF_VHI + off) = pack_bf2(ha, hb);
                *(uint32_t*)(fsm + OFF_VLO + off) = pack_bf2(la, lb);
            }
        }
        __syncthreads();

        if (ks > wmax) continue;                 // warp-level causal skip
        const bool need_mask = (ks + FK - 1) > wmin;

        // ---- S = Q K^T (3-pass split) ----
        float sc[2][8][4];
        #pragma unroll
        for (int i = 0; i < 2; i++)
            #pragma unroll
            for (int j = 0; j < 8; j++)
                #pragma unroll
                for (int r = 0; r < 4; r++) sc[i][j][r] = 0.f;

        #pragma unroll
        for (int s = 0; s < 4; s++) {
            uint32_t qh[2][4], ql[2][4];
            #pragma unroll
            for (int i = 0; i < 2; i++) {
                const int qr = w * 32 + i * 16 + (lane & 7) + (lane & 8);
                const int ch = s * 2 + (lane >> 4);
                ldsm_x4(qh[i], swz(sb + OFF_QHI, qr, ch));
                ldsm_x4(ql[i], swz(sb + OFF_QLO, qr, ch));
            }
            uint32_t kh[8][2], kl[8][2];
            #pragma unroll
            for (int j = 0; j < 8; j++) {
                const int kr = j * 8 + (lane & 7);
                const int ch = s * 2 + ((lane >> 3) & 1);
                ldsm_x2(kh[j], swz(sb + OFF_KHI, kr, ch));
                ldsm_x2(kl[j], swz(sb + OFF_KLO, kr, ch));
            }
            #pragma unroll
            for (int i = 0; i < 2; i++)
                #pragma unroll
                for (int j = 0; j < 8; j++) {
                    mma_bf16(sc[i][j], qh[i], kh[j]);
                    mma_bf16(sc[i][j], ql[i], kh[j]);
                    mma_bf16(sc[i][j], qh[i], kl[j]);
                }
        }

        // ---- scale + causal mask + online softmax ----
        const int g = lane >> 2, tq = lane & 3;
        float mx[4] = {-1e30f, -1e30f, -1e30f, -1e30f};
        #pragma unroll
        for (int i = 0; i < 2; i++)
            #pragma unroll
            for (int j = 0; j < 8; j++)
                #pragma unroll
                for (int r = 0; r < 4; r++) {
                    float val = sc[i][j][r] * scale;
                    if (need_mask) {
                        const int row = wmin + i * 16 + (r >> 1) * 8 + g;
                        const int col = ks + j * 8 + 2 * tq + (r & 1);
                        if (col > row) val = -1e30f;
                    }
                    sc[i][j][r] = val;
                    const int slot = i * 2 + (r >> 1);
                    mx[slot] = fmaxf(mx[slot], val);
                }
        #pragma unroll
        for (int slot = 0; slot < 4; slot++) {
            mx[slot] = fmaxf(mx[slot], __shfl_xor_sync(0xffffffffu, mx[slot], 1));
            mx[slot] = fmaxf(mx[slot], __shfl_xor_sync(0xffffffffu, mx[slot], 2));
        }
        float sf[4], mn[4];
        #pragma unroll
        for (int slot = 0; slot < 4; slot++) {
            mn[slot] = fmaxf(mrow[slot], mx[slot]);
            sf[slot] = __expf(mrow[slot] - mn[slot]);
            mrow[slot] = mn[slot];
        }
        float ps[4] = {0.f, 0.f, 0.f, 0.f};
        #pragma unroll
        for (int i = 0; i < 2; i++)
            #pragma unroll
            for (int j = 0; j < 8; j++)
                #pragma unroll
                for (int r = 0; r < 4; r++) {
                    const int slot = i * 2 + (r >> 1);
                    float p = __expf(sc[i][j][r] - mn[slot]);
                    sc[i][j][r] = p;
                    ps[slot] += p;
                }
        #pragma unroll
        for (int slot = 0; slot < 4; slot++) {
            ps[slot] += __shfl_xor_sync(0xffffffffu, ps[slot], 1);
            ps[slot] += __shfl_xor_sync(0xffffffffu, ps[slot], 2);
            lrow[slot] = lrow[slot] * sf[slot] + ps[slot];
        }
        #pragma unroll
        for (int i = 0; i < 2; i++)
            #pragma unroll
            for (int j = 0; j < 8; j++)
                #pragma unroll
                for (int r = 0; r < 4; r++)
                    o[i][j][r] *= sf[i * 2 + (r >> 1)];

        // ---- O += P V (3-pass split; P fragments built from sc) ----
        #pragma unroll
        for (int t = 0; t < 4; t++) {
            uint32_t ah[2][4], al[2][4];
            #pragma unroll
            for (int i = 0; i < 2; i++) {
                #pragma unroll
                for (int half = 0; half < 2; half++) {        // tiles 2t, 2t+1
                    const float p0 = sc[i][2 * t + half][0];
                    const float p1 = sc[i][2 * t + half][1];
                    const float p2 = sc[i][2 * t + half][2];
                    const float p3 = sc[i][2 * t + half][3];
                    __nv_bfloat16 h0 = __float2bfloat16(p0), h1 = __float2bfloat16(p1);
                    __nv_bfloat16 h2 = __float2bfloat16(p2), h3 = __float2bfloat16(p3);
                    ah[i][half * 2 + 0] = pack_bf2(h0, h1);
                    ah[i][half * 2 + 1] = pack_bf2(h2, h3);
                    al[i][half * 2 + 0] = pack_bf2(
                        __float2bfloat16(p0 - __bfloat162float(h0)),
                        __float2bfloat16(p1 - __bfloat162float(h1)));
                    al[i][half * 2 + 1] = pack_bf2(
                        __float2bfloat16(p2 - __bfloat162float(h2)),
                        __float2bfloat16(p3 - __bfloat162float(h3)));
                }
            }
            uint32_t vh[8][2], vl[8][2];
            #pragma unroll
            for (int jd = 0; jd < 8; jd++) {
                const int vr = jd * 8 + (lane & 7);
                const int ch = t * 2 + ((lane >> 3) & 1);
                ldsm_x2(vh[jd], swz(sb + OFF_VHI, vr, ch));
                ldsm_x2(vl[jd], swz(sb + OFF_VLO, vr, ch));
            }
            #pragma unroll
            for (int i = 0; i < 2; i++)
                #pragma unroll
                for (int jd = 0; jd < 8; jd++) {
                    mma_bf16(o[i][jd], ah[i], vh[jd]);
                    mma_bf16(o[i][jd], al[i], vh[jd]);
                    mma_bf16(o[i][jd], ah[i], vl[jd]);
                }
        }
    }

    // ---- epilogue ----
    float inv[4];
    #pragma unroll
    for (int slot = 0; slot < 4; slot++) inv[slot] = 1.f / lrow[slot];

    const int g = lane >> 2, tq = lane & 3;
    #pragma unroll
    for (int i = 0; i < 2; i++)
        #pragma unroll
        for (int jd = 0; jd < 8; jd++)
            #pragma unroll
            for (int h2 = 0; h2 < 2; h2++) {
                const int row = qs + w * 32 + i * 16 + h2 * 8 + g;
                const int col = hh * HDIM + jd * 8 + 2 * tq;
                const float iv = inv[i * 2 + h2];
                float2 val = { o[i][jd][h2 * 2] * iv, o[i][jd][h2 * 2 + 1] * iv };
                *(float2*)(O + ((size_t)row * BATCH + b) * EMB + col) = val;
            }
}

// ---------------------------------------------------------------------------
// Launch
// Inputs: query, key, value, Wq, bq, Wk, bk, Wv, bv, Wo, bo
// ---------------------------------------------------------------------------
extern "C" void kernel_launch(void* const* d_in, const int* in_sizes, int n_in,
                              void* d_out, int out_size)
{
    (void)in_sizes; (void)n_in; (void)out_size;
    const float* query = (const float*)d_in[0];
    const float* key   = (const float*)d_in[1];
    const float* value = (const float*)d_in[2];
    const float* Wq    = (const float*)d_in[3];
    const float* bq    = (const float*)d_in[4];
    const float* Wk    = (const float*)d_in[5];
    const float* bk    = (const float*)d_in[6];
    const float* Wv    = (const float*)d_in[7];
    const float* bv    = (const float*)d_in[8];
    const float* Wo    = (const float*)d_in[9];
    const float* bo    = (const float*)d_in[10];
    float* out = (float*)d_out;

    float *q, *k, *v, *ao;
    __nv_bfloat16 *xs, *ws;
    cudaGetSymbolAddress((void**)&q,  g_q);
    cudaGetSymbolAddress((void**)&k,  g_k);
    cudaGetSymbolAddress((void**)&v,  g_v);
    cudaGetSymbolAddress((void**)&ao, g_ao);
    cudaGetSymbolAddress((void**)&xs, g_xs);
    cudaGetSymbolAddress((void**)&ws, g_ws);

    cudaFuncSetAttribute(flash_tc_kernel,
                         cudaFuncAttributeMaxDynamicSharedMemorySize, FLASH_SMEM);

    const int gsx = MROWS * EMB / (8 * 256);
    const int gsw = EMB * EMB / (8 * 256);
    dim3 ggrid(EMB / BN, MROWS / BM);

    split3_kernel<<<gsx, 256>>>(query, xs, 0);
    split3_kernel<<<gsw, 256>>>(Wq, ws, 1);
    gemm_mma_kernel<<<ggrid, 256>>>(xs, ws, bq, q);

    split3_kernel<<<gsx, 256>>>(key, xs, 0);
    split3_kernel<<<gsw, 256>>>(Wk, ws, 1);
    gemm_mma_kernel<<<ggrid, 256>>>(xs, ws, bk, k);

    split3_kernel<<<gsx, 256>>>(value, xs, 0);
    split3_kernel<<<gsw, 256>>>(Wv, ws, 1);
    gemm_mma_kernel<<<ggrid, 256>>>(xs, ws, bv, v);

    dim3 agrid(S_LEN / FQ, HEADS, BATCH);   // (16, 16, 2)
    flash_tc_kernel<<<agrid, 128, FLASH_SMEM>>>(q, k, v, ao);

    split3_kernel<<<gsx, 256>>>(ao, xs, 0);
    split3_kernel<<<gsw, 256>>>(Wo, ws, 1);
    gemm_mma_kernel<<<ggrid, 256>>>(xs, ws, bo, out);
}

// round 6
// speedup vs baseline: 5.2444x; 1.0056x over previous
#include <cuda_runtime.h>
#include <cuda_bf16.h>
#include <cstdint>

// ---------------------------------------------------------------------------
// Problem constants
// ---------------------------------------------------------------------------
#define S_LEN 2048
#define BATCH 2
#define EMB   1024
#define HEADS 16
#define HDIM  64
#define MROWS (S_LEN * BATCH)      // 4096
#define K3    3072                 // 3 * EMB (bf16x3 split concat along K)

// ---------------------------------------------------------------------------
// Device scratch (allocation-free rule: __device__ globals)
// ---------------------------------------------------------------------------
__device__ float g_q [MROWS * EMB];
__device__ float g_k [MROWS * EMB];
__device__ float g_v [MROWS * EMB];
__device__ float g_ao[MROWS * EMB];

__device__ __align__(128) __nv_bfloat16 g_xs[MROWS * K3];   // 24 MB
__device__ __align__(128) __nv_bfloat16 g_ws[EMB * K3];     //  6 MB

// flash pre-split buffers (bf16 hi/lo):
// Q/K: [b][h][s][d] ; V transposed: [b][h][d][s]
#define BHSD (BATCH * HEADS * S_LEN * HDIM)      // 4M elems, 8MB each
__device__ __align__(128) __nv_bfloat16 g_fqh[BHSD];
__device__ __align__(128) __nv_bfloat16 g_fql[BHSD];
__device__ __align__(128) __nv_bfloat16 g_fkh[BHSD];
__device__ __align__(128) __nv_bfloat16 g_fkl[BHSD];
__device__ __align__(128) __nv_bfloat16 g_fvh[BHSD];
__device__ __align__(128) __nv_bfloat16 g_fvl[BHSD];

// ---------------------------------------------------------------------------
// PTX helpers (baseline sm_80+ only — harness lowers via .target sm_103
// which rejects tcgen05 / 'a'-suffix features)
// ---------------------------------------------------------------------------
__device__ __forceinline__ uint32_t smem_to_u32(const void* p) {
    uint32_t a;
    asm("{ .reg .u64 t; cvta.to.shared.u64 t, %1; cvt.u32.u64 %0, t; }"
        : "=r"(a) : "l"(p));
    return a;
}

__device__ __forceinline__ void cp_async16(uint32_t s, const void* g) {
    asm volatile("cp.async.cg.shared.global [%0], [%1], 16;"
                 :: "r"(s), "l"(g) : "memory");
}
#define CP_COMMIT() asm volatile("cp.async.commit_group;" ::: "memory")
#define CP_WAIT(n)  asm volatile("cp.async.wait_group %0;" :: "n"(n) : "memory")

__device__ __forceinline__ void ldsm_x4(uint32_t* r, uint32_t addr) {
    asm volatile("ldmatrix.sync.aligned.m8n8.x4.shared.b16 {%0,%1,%2,%3}, [%4];"
        : "=r"(r[0]), "=r"(r[1]), "=r"(r[2]), "=r"(r[3]) : "r"(addr));
}
__device__ __forceinline__ void ldsm_x2(uint32_t* r, uint32_t addr) {
    asm volatile("ldmatrix.sync.aligned.m8n8.x2.shared.b16 {%0,%1}, [%2];"
        : "=r"(r[0]), "=r"(r[1]) : "r"(addr));
}

__device__ __forceinline__ void mma_bf16(float* d, const uint32_t* a, const uint32_t* b) {
    asm volatile(
        "mma.sync.aligned.m16n8k16.row.col.f32.bf16.bf16.f32 "
        "{%0,%1,%2,%3}, {%4,%5,%6,%7}, {%8,%9}, {%0,%1,%2,%3};"
        : "+f"(d[0]), "+f"(d[1]), "+f"(d[2]), "+f"(d[3])
        : "r"(a[0]), "r"(a[1]), "r"(a[2]), "r"(a[3]), "r"(b[0]), "r"(b[1]));
}

__device__ __forceinline__ uint32_t pack_bf2(__nv_bfloat16 a, __nv_bfloat16 b) {
    __nv_bfloat162 t; t.x = a; t.y = b;
    return *(uint32_t*)&t;
}

struct alignas(16) bf16x8 { __nv_bfloat16 v[8]; };

// ---------------------------------------------------------------------------
// Split kernel for GEMM operands: fp32 [rows,1024] -> bf16 [rows,3072]
// mode 0 (activations): hi | lo | hi ; mode 1 (weights): hi | hi | lo
// ---------------------------------------------------------------------------
__global__ __launch_bounds__(256) void split3_kernel(
    const float* __restrict__ X, __nv_bfloat16* __restrict__ out, int mode)
{
    const uint32_t t = blockIdx.x * 256u + threadIdx.x;
    const uint32_t e = t * 8u;
    const uint32_t m = e >> 10, k = e & 1023u;

    float x[8];
    *(float4*)&x[0] = *(const float4*)(X + e);
    *(float4*)&x[4] = *(const float4*)(X + e + 4);

    bf16x8 H, L;
    #pragma unroll
    for (int i = 0; i < 8; i++) {
        __nv_bfloat16 h = __float2bfloat16(x[i]);
        H.v[i] = h;
        L.v[i] = __float2bfloat16(x[i] - __bfloat162float(h));
    }

    __nv_bfloat16* rb = out + (size_t)m * K3 + k;
    if (mode == 0) {
        *(bf16x8*)(rb)        = H;
        *(bf16x8*)(rb + 1024) = L;
        *(bf16x8*)(rb + 2048) = H;
    } else {
        *(bf16x8*)(rb)        = H;
        *(bf16x8*)(rb + 1024) = H;
        *(bf16x8*)(rb + 2048) = L;
    }
}

// ---------------------------------------------------------------------------
// Pre-split for flash Q/K: fp32 [m=(s,b)][h*64+d] -> bf16 hi/lo [b][h][s][d]
// scale folded into the split (exact for powers of two).
// ---------------------------------------------------------------------------
__global__ __launch_bounds__(256) void qk_presplit_kernel(
    const float* __restrict__ X,
    __nv_bfloat16* __restrict__ oh, __nv_bfloat16* __restrict__ ol, float scale)
{
    const uint32_t t = blockIdx.x * 256u + threadIdx.x;
    const uint32_t e = t * 8u;
    const uint32_t m = e >> 10, k = e & 1023u;
    const uint32_t h = k >> 6, d = k & 63u;
    const uint32_t s = m >> 1, b = m & 1u;

    float x[8];
    *(float4*)&x[0] = *(const float4*)(X + e);
    *(float4*)&x[4] = *(const float4*)(X + e + 4);

    bf16x8 H, L;
    #pragma unroll
    for (int i = 0; i < 8; i++) {
        const float xv = x[i] * scale;
        __nv_bfloat16 hb = __float2bfloat16(xv);
        H.v[i] = hb;
        L.v[i] = __float2bfloat16(xv - __bfloat162float(hb));
    }
    const size_t dst = (((size_t)(b * 16 + h) * S_LEN) + s) * 64 + d;
    *(bf16x8*)(oh + dst) = H;
    *(bf16x8*)(ol + dst) = L;
}

// ---------------------------------------------------------------------------
// Pre-split + transpose for flash V: fp32 -> bf16 hi/lo [b][h][d][s]
// Block handles one (b, h, 64-key tile); smem transpose.
// Row stride 68 floats (272B): keeps every float4 access 16B-aligned
// (65 floats broke alignment -> misaligned-address trap in round 5).
// ---------------------------------------------------------------------------
__global__ __launch_bounds__(256) void v_presplit_kernel(
    const float* __restrict__ V,
    __nv_bfloat16* __restrict__ vh, __nv_bfloat16* __restrict__ vl)
{
    __shared__ float ts[64][68];
    const int st_ = blockIdx.x, h = blockIdx.y, b = blockIdx.z;
    const int t = threadIdx.x;

    {
        const int r = t >> 2, c0 = (t & 3) * 16;
        const float* vp = V + ((size_t)(st_ * 64 + r) * BATCH + b) * EMB + h * HDIM + c0;
        #pragma unroll
        for (int i = 0; i < 4; i++)
            *(float4*)&ts[r][c0 + i * 4] = *(const float4*)&vp[i * 4];
    }
    __syncthreads();

    const int d = t >> 2, s0 = (t & 3) * 16;
    bf16x8 H0, H1, L0, L1;
    #pragma unroll
    for (int i = 0; i < 16; i++) {
        const float x = ts[s0 + i][d];
        __nv_bfloat16 hb = __float2bfloat16(x);
        __nv_bfloat16 lb = __float2bfloat16(x - __bfloat162float(hb));
        if (i < 8) { H0.v[i] = hb; L0.v[i] = lb; }
        else       { H1.v[i - 8] = hb; L1.v[i - 8] = lb; }
    }
    const size_t dst = (((size_t)(b * 16 + h) * 64) + d) * S_LEN + st_ * 64 + s0;
    *(bf16x8*)(vh + dst)     = H0;
    *(bf16x8*)(vh + dst + 8) = H1;
    *(bf16x8*)(vl + dst)     = L0;
    *(bf16x8*)(vl + dst + 8) = L1;
}

// ---------------------------------------------------------------------------
// bf16 mma.sync GEMM: Y[4096,1024] = Xs[4096,3072]·Ws[1024,3072]^T + bias
// CTA tile 256x128, BK=32, 512 threads (16 warps, warp tile 64x32),
// double-buffered cp.async, swizzled smem, fp32 accum, fused bias.
// ---------------------------------------------------------------------------
#define BM 256
#define BN 128
#define BK 32
#define NKT (K3 / BK)
#define GSTAGE 24576           // A 16KB + B 8KB

__global__ __launch_bounds__(512) void gemm_mma_kernel(
    const __nv_bfloat16* __restrict__ A,
    const __nv_bfloat16* __restrict__ B,
    const float* __restrict__ bias, float* __restrict__ Y)
{
    __shared__ __align__(128) char smem[2 * GSTAGE];
    const uint32_t sb = smem_to_u32(smem);
    const int tid  = threadIdx.x;
    const int lane = tid & 31, wid = tid >> 5;
    const int bn = blockIdx.x, bm = blockIdx.y;
    const int wm = (wid >> 2) * 64;        // 0/64/128/192
    const int wn = (wid & 3) * 32;         // 0/32/64/96

    float acc[4][4][4];
    #pragma unroll
    for (int i = 0; i < 4; i++)
        #pragma unroll
        for (int j = 0; j < 4; j++)
            #pragma unroll
            for (int r = 0; r < 4; r++) acc[i][j][r] = 0.f;

    const __nv_bfloat16* Ab = A + (size_t)bm * BM * K3;
    const __nv_bfloat16* Bb = B + (size_t)bn * BN * K3;

    // loaders: A 256 rows x 4 chunks (2/thread), B 128 rows x 4 chunks (1/thread)
    const int ra = tid >> 1;               // 0..255
    const int ca = (tid & 1) * 2;          // chunk base 0 / 2
    const int rb = tid >> 2, cb = tid & 3;

    #define LOAD_TILE(kt, buf) do {                                              \
        const uint32_t st = sb + (buf) * GSTAGE;                                 \
        const size_t kb = (size_t)(kt) * BK;                                     \
        cp_async16(st + ra * 64 + (((ca)     ^ ((ra >> 1) & 3)) << 4),           \
                   Ab + (size_t)ra * K3 + kb + (ca) * 8);                        \
        cp_async16(st + ra * 64 + (((ca + 1) ^ ((ra >> 1) & 3)) << 4),           \
                   Ab + (size_t)ra * K3 + kb + (ca + 1) * 8);                    \
        cp_async16(st + 16384 + rb * 64 + ((cb ^ ((rb >> 1) & 3)) << 4),         \
                   Bb + (size_t)rb * K3 + kb + cb * 8);                          \
        CP_COMMIT();                                                             \
    } while (0)

    LOAD_TILE(0, 0);

    for (int kt = 0; kt < NKT; kt++) {
        const int buf = kt & 1;
        if (kt + 1 < NKT) {
            LOAD_TILE(kt + 1, buf ^ 1);
            CP_WAIT(1);
        } else {
            CP_WAIT(0);
        }
        __syncthreads();

        const uint32_t st = sb + buf * GSTAGE;
        #pragma unroll
        for (int s = 0; s < 2; s++) {
            uint32_t af[4][4], bf[4][2];
            #pragma unroll
            for (int i = 0; i < 4; i++) {
                const int row = wm + i * 16 + (lane & 7) + (lane & 8);
                const int ch  = s * 2 + (lane >> 4);
                ldsm_x4(af[i], st + row * 64 + ((ch ^ ((row >> 1) & 3)) << 4));
            }
            #pragma unroll
            for (int j = 0; j < 4; j++) {
                const int row = wn + j * 8 + (lane & 7);
                const int ch  = s * 2 + ((lane >> 3) & 1);
                ldsm_x2(bf[j], st + 16384 + row * 64 + ((ch ^ ((row >> 1) & 3)) << 4));
            }
            #pragma unroll
            for (int i = 0; i < 4; i++)
                #pragma unroll
                for (int j = 0; j < 4; j++)
                    mma_bf16(acc[i][j], af[i], bf[j]);
        }
        __syncthreads();
    }
    #undef LOAD_TILE

    #pragma unroll
    for (int j = 0; j < 4; j++) {
        const int col = bn * BN + wn + j * 8 + (lane & 3) * 2;
        const float b0 = bias[col], b1 = bias[col + 1];
        #pragma unroll
        for (int i = 0; i < 4; i++) {
            const int row = bm * BM + wm + i * 16 + (lane >> 2);
            float2 v0 = { acc[i][j][0] + b0, acc[i][j][1] + b1 };
            float2 v1 = { acc[i][j][2] + b0, acc[i][j][3] + b1 };
            *(float2*)(Y + (size_t)row * EMB + col)       = v0;
            *(float2*)(Y + (size_t)(row + 8) * EMB + col) = v1;
        }
    }
}

// ---------------------------------------------------------------------------
// Tensor-core causal flash attention with pre-split bf16 inputs + cp.async
// double-buffered K/V tiles. 128 q rows x (head, batch), 4 warps.
// Smem: Qhi/Qlo 2x16KB + 2 stages x {Khi,Klo 8KB; VhiT,VloT 8KB} = 96KB.
// ---------------------------------------------------------------------------
#define FQ 128
#define FK 64
#define FOFF_QLO 16384
#define FOFF_ST  32768          // stage s at FOFF_ST + s*32768
#define FLASH_SMEM 98304

__device__ __forceinline__ uint32_t fswz(uint32_t base, int row, int ch) {
    return base + (uint32_t)(row * 128) + (uint32_t)(((ch ^ (row & 7)) & 7) << 4);
}

__global__ __launch_bounds__(128, 1) void flash_tc_kernel(
    const __nv_bfloat16* __restrict__ QH, const __nv_bfloat16* __restrict__ QL,
    const __nv_bfloat16* __restrict__ KH, const __nv_bfloat16* __restrict__ KL,
    const __nv_bfloat16* __restrict__ VH, const __nv_bfloat16* __restrict__ VL,
    float* __restrict__ O)
{
    extern __shared__ __align__(128) char fsm[];
    const uint32_t sb = smem_to_u32(fsm);

    const int qt = (int)(gridDim.x - 1) - (int)blockIdx.x;  // heavy tiles first
    const int hh = blockIdx.y;
    const int b  = blockIdx.z;
    const int tid = threadIdx.x, lane = tid & 31, w = tid >> 5;
    const int qs = qt * FQ;
    const size_t bh = (size_t)(b * 16 + hh);

    const __nv_bfloat16* qhp = QH + (bh * S_LEN + qs) * 64 + (size_t)tid * 64;
    const __nv_bfloat16* qlp = QL + (bh * S_LEN + qs) * 64 + (size_t)tid * 64;
    const __nv_bfloat16* khp = KH + bh * S_LEN * 64;
    const __nv_bfloat16* klp = KL + bh * S_LEN * 64;
    const __nv_bfloat16* vhp = VH + bh * 64 * S_LEN;
    const __nv_bfloat16* vlp = VL + bh * 64 * S_LEN;

    // ---- Q: one group ----
    #pragma unroll
    for (int c = 0; c < 8; c++) {
        cp_async16(fswz(sb,            tid, c), qhp + c * 8);
        cp_async16(fswz(sb + FOFF_QLO, tid, c), qlp + c * 8);
    }
    CP_COMMIT();

    // ---- stage loader: 64 rows x 8 chunks per buffer, 4 buffers ----
    const int lr = tid >> 1;           // row 0..63
    const int lc = (tid & 1) * 4;      // chunk base 0 / 4
    #define FLOAD(kt_, s_) do {                                                  \
        const uint32_t st_ = sb + FOFF_ST + (s_) * 32768;                        \
        const int ks_ = (kt_) * FK;                                              \
        _Pragma("unroll")                                                        \
        for (int i = 0; i < 4; i++) {                                            \
            const int ch = lc + i;                                               \
            cp_async16(fswz(st_,         lr, ch), khp + (size_t)(ks_ + lr) * 64 + ch * 8); \
            cp_async16(fswz(st_ +  8192, lr, ch), klp + (size_t)(ks_ + lr) * 64 + ch * 8); \
            cp_async16(fswz(st_ + 16384, lr, ch), vhp + (size_t)lr * S_LEN + ks_ + ch * 8); \
            cp_async16(fswz(st_ + 24576, lr, ch), vlp + (size_t)lr * S_LEN + ks_ + ch * 8); \
        }                                                                        \
        CP_COMMIT();                                                             \
    } while (0)

    FLOAD(0, 0);

    float o[2][8][4];
    #pragma unroll
    for (int i = 0; i < 2; i++)
        #pragma unroll
        for (int j = 0; j < 8; j++)
            #pragma unroll
            for (int r = 0; r < 4; r++) o[i][j][r] = 0.f;
    float mrow[4] = {-1e30f, -1e30f, -1e30f, -1e30f};
    float lrow[4] = {0.f, 0.f, 0.f, 0.f};

    const int wmin = qs + w * 32;
    const int wmax = wmin + 31;
    const int nkt = 2 * qt + 2;

    for (int kt = 0; kt < nkt; kt++) {
        if (kt + 1 < nkt) {
            FLOAD(kt + 1, (kt + 1) & 1);
            CP_WAIT(1);
        } else {
            CP_WAIT(0);
        }
        __syncthreads();

        const int ks = kt * FK;
        if (ks <= wmax) {
            const uint32_t stv = sb + FOFF_ST + (uint32_t)(kt & 1) * 32768;
            const uint32_t KHIb = stv, KLOb = stv + 8192;
            const uint32_t VHIb = stv + 16384, VLOb = stv + 24576;
            const bool need_mask = (ks + FK - 1) > wmin;

            // ---- S = Q K^T (3-pass split; scale pre-folded into Q) ----
            float sc[2][8][4];
            #pragma unroll
            for (int i = 0; i < 2; i++)
                #pragma unroll
                for (int j = 0; j < 8; j++)
                    #pragma unroll
                    for (int r = 0; r < 4; r++) sc[i][j][r] = 0.f;

            #pragma unroll
            for (int s = 0; s < 4; s++) {
                uint32_t qh[2][4], ql[2][4];
                #pragma unroll
                for (int i = 0; i < 2; i++) {
                    const int qr = w * 32 + i * 16 + (lane & 7) + (lane & 8);
                    const int ch = s * 2 + (lane >> 4);
                    ldsm_x4(qh[i], fswz(sb,            qr, ch));
                    ldsm_x4(ql[i], fswz(sb + FOFF_QLO, qr, ch));
                }
                uint32_t kh[8][2], kl[8][2];
                #pragma unroll
                for (int j = 0; j < 8; j++) {
                    const int kr = j * 8 + (lane & 7);
                    const int ch = s * 2 + ((lane >> 3) & 1);
                    ldsm_x2(kh[j], fswz(KHIb, kr, ch));
                    ldsm_x2(kl[j], fswz(KLOb, kr, ch));
                }
                #pragma unroll
                for (int i = 0; i < 2; i++)
                    #pragma unroll
                    for (int j = 0; j < 8; j++) {
                        mma_bf16(sc[i][j], qh[i], kh[j]);
                        mma_bf16(sc[i][j], ql[i], kh[j]);
                        mma_bf16(sc[i][j], qh[i], kl[j]);
                    }
            }

            // ---- causal mask + online softmax ----
            const int g = lane >> 2, tq = lane & 3;
            float mx[4] = {-1e30f, -1e30f, -1e30f, -1e30f};
            #pragma unroll
            for (int i = 0; i < 2; i++)
                #pragma unroll
                for (int j = 0; j < 8; j++)
                    #pragma unroll
                    for (int r = 0; r < 4; r++) {
                        float val = sc[i][j][r];
                        if (need_mask) {
                            const int row = wmin + i * 16 + (r >> 1) * 8 + g;
                            const int col = ks + j * 8 + 2 * tq + (r & 1);
                            if (col > row) val = -1e30f;
                        }
                        sc[i][j][r] = val;
                        const int slot = i * 2 + (r >> 1);
                        mx[slot] = fmaxf(mx[slot], val);
                    }
            #pragma unroll
            for (int slot = 0; slot < 4; slot++) {
                mx[slot] = fmaxf(mx[slot], __shfl_xor_sync(0xffffffffu, mx[slot], 1));
                mx[slot] = fmaxf(mx[slot], __shfl_xor_sync(0xffffffffu, mx[slot], 2));
            }
            float sf[4], mn[4];
            #pragma unroll
            for (int slot = 0; slot < 4; slot++) {
                mn[slot] = fmaxf(mrow[slot], mx[slot]);
                sf[slot] = __expf(mrow[slot] - mn[slot]);
                mrow[slot] = mn[slot];
            }
            float ps[4] = {0.f, 0.f, 0.f, 0.f};
            #pragma unroll
            for (int i = 0; i < 2; i++)
                #pragma unroll
                for (int j = 0; j < 8; j++)
                    #pragma unroll
                    for (int r = 0; r < 4; r++) {
                        const int slot = i * 2 + (r >> 1);
                        float p = __expf(sc[i][j][r] - mn[slot]);
                        sc[i][j][r] = p;
                        ps[slot] += p;
                    }
            #pragma unroll
            for (int slot = 0; slot < 4; slot++) {
                ps[slot] += __shfl_xor_sync(0xffffffffu, ps[slot], 1);
                ps[slot] += __shfl_xor_sync(0xffffffffu, ps[slot], 2);
                lrow[slot] = lrow[slot] * sf[slot] + ps[slot];
            }
            #pragma unroll
            for (int i = 0; i < 2; i++)
                #pragma unroll
                for (int j = 0; j < 8; j++)
                    #pragma unroll
                    for (int r = 0; r < 4; r++)
                        o[i][j][r] *= sf[i * 2 + (r >> 1)];

            // ---- O += P V (3-pass split) ----
            #pragma unroll
            for (int t = 0; t < 4; t++) {
                uint32_t ah[2][4], al[2][4];
                #pragma unroll
                for (int i = 0; i < 2; i++) {
                    #pragma unroll
                    for (int half = 0; half < 2; half++) {
                        const float p0 = sc[i][2 * t + half][0];
                        const float p1 = sc[i][2 * t + half][1];
                        const float p2 = sc[i][2 * t + half][2];
                        const float p3 = sc[i][2 * t + half][3];
                        __nv_bfloat16 h0 = __float2bfloat16(p0), h1 = __float2bfloat16(p1);
                        __nv_bfloat16 h2 = __float2bfloat16(p2), h3 = __float2bfloat16(p3);
                        ah[i][half * 2 + 0] = pack_bf2(h0, h1);
                        ah[i][half * 2 + 1] = pack_bf2(h2, h3);
                        al[i][half * 2 + 0] = pack_bf2(
                            __float2bfloat16(p0 - __bfloat162float(h0)),
                            __float2bfloat16(p1 - __bfloat162float(h1)));
                        al[i][half * 2 + 1] = pack_bf2(
                            __float2bfloat16(p2 - __bfloat162float(h2)),
                            __float2bfloat16(p3 - __bfloat162float(h3)));
                    }
                }
                uint32_t vh[8][2], vl[8][2];
                #pragma unroll
                for (int jd = 0; jd < 8; jd++) {
                    const int vr = jd * 8 + (lane & 7);
                    const int ch = t * 2 + ((lane >> 3) & 1);
                    ldsm_x2(vh[jd], fswz(VHIb, vr, ch));
                    ldsm_x2(vl[jd], fswz(VLOb, vr, ch));
                }
                #pragma unroll
                for (int i = 0; i < 2; i++)
                    #pragma unroll
                    for (int jd = 0; jd < 8; jd++) {
                        mma_bf16(o[i][jd], ah[i], vh[jd]);
                        mma_bf16(o[i][jd], al[i], vh[jd]);
                        mma_bf16(o[i][jd], ah[i], vl[jd]);
                    }
            }
        }
        __syncthreads();
    }
    #undef FLOAD

    // ---- epilogue ----
    float inv[4];
    #pragma unroll
    for (int slot = 0; slot < 4; slot++) inv[slot] = 1.f / lrow[slot];

    const int g = lane >> 2, tq = lane & 3;
    #pragma unroll
    for (int i = 0; i < 2; i++)
        #pragma unroll
        for (int jd = 0; jd < 8; jd++)
            #pragma unroll
            for (int h2 = 0; h2 < 2; h2++) {
                const int row = qs + w * 32 + i * 16 + h2 * 8 + g;
                const int col = hh * HDIM + jd * 8 + 2 * tq;
                const float iv = inv[i * 2 + h2];
                float2 val = { o[i][jd][h2 * 2] * iv, o[i][jd][h2 * 2 + 1] * iv };
                *(float2*)(O + ((size_t)row * BATCH + b) * EMB + col) = val;
            }
}

// ---------------------------------------------------------------------------
// Launch
// Inputs: query, key, value, Wq, bq, Wk, bk, Wv, bv, Wo, bo
// ---------------------------------------------------------------------------
extern "C" void kernel_launch(void* const* d_in, const int* in_sizes, int n_in,
                              void* d_out, int out_size)
{
    (void)in_sizes; (void)n_in; (void)out_size;
    const float* query = (const float*)d_in[0];
    const float* key   = (const float*)d_in[1];
    const float* value = (const float*)d_in[2];
    const float* Wq    = (const float*)d_in[3];
    const float* bq    = (const float*)d_in[4];
    const float* Wk    = (const float*)d_in[5];
    const float* bk    = (const float*)d_in[6];
    const float* Wv    = (const float*)d_in[7];
    const float* bv    = (const float*)d_in[8];
    const float* Wo    = (const float*)d_in[9];
    const float* bo    = (const float*)d_in[10];
    float* out = (float*)d_out;

    float *q, *k, *v, *ao;
    __nv_bfloat16 *xs, *ws, *fqh, *fql, *fkh, *fkl, *fvh, *fvl;
    cudaGetSymbolAddress((void**)&q,   g_q);
    cudaGetSymbolAddress((void**)&k,   g_k);
    cudaGetSymbolAddress((void**)&v,   g_v);
    cudaGetSymbolAddress((void**)&ao,  g_ao);
    cudaGetSymbolAddress((void**)&xs,  g_xs);
    cudaGetSymbolAddress((void**)&ws,  g_ws);
    cudaGetSymbolAddress((void**)&fqh, g_fqh);
    cudaGetSymbolAddress((void**)&fql, g_fql);
    cudaGetSymbolAddress((void**)&fkh, g_fkh);
    cudaGetSymbolAddress((void**)&fkl, g_fkl);
    cudaGetSymbolAddress((void**)&fvh, g_fvh);
    cudaGetSymbolAddress((void**)&fvl, g_fvl);

    cudaFuncSetAttribute(flash_tc_kernel,
                         cudaFuncAttributeMaxDynamicSharedMemorySize, FLASH_SMEM);

    const int gsx = MROWS * EMB / (8 * 256);   // 2048
    const int gsw = EMB * EMB / (8 * 256);     //  512
    dim3 ggrid(EMB / BN, MROWS / BM);          // (8, 16)

    split3_kernel<<<gsx, 256>>>(query, xs, 0);
    split3_kernel<<<gsw, 256>>>(Wq, ws, 1);
    gemm_mma_kernel<<<ggrid, 512>>>(xs, ws, bq, q);

    split3_kernel<<<gsx, 256>>>(key, xs, 0);
    split3_kernel<<<gsw, 256>>>(Wk, ws, 1);
    gemm_mma_kernel<<<ggrid, 512>>>(xs, ws, bk, k);

    split3_kernel<<<gsx, 256>>>(value, xs, 0);
    split3_kernel<<<gsw, 256>>>(Wv, ws, 1);
    gemm_mma_kernel<<<ggrid, 512>>>(xs, ws, bv, v);

    qk_presplit_kernel<<<gsx, 256>>>(q, fqh, fql, 0.125f);
    qk_presplit_kernel<<<gsx, 256>>>(k, fkh, fkl, 1.0f);
    dim3 vgrid(S_LEN / 64, HEADS, BATCH);      // (32, 16, 2)
    v_presplit_kernel<<<vgrid, 256>>>(v, fvh, fvl);

    dim3 agrid(S_LEN / FQ, HEADS, BATCH);      // (16, 16, 2)
    flash_tc_kernel<<<agrid, 128, FLASH_SMEM>>>(fqh, fql, fkh, fkl, fvh, fvl, ao);

    split3_kernel<<<gsx, 256>>>(ao, xs, 0);
    split3_kernel<<<gsw, 256>>>(Wo, ws, 1);
    gemm_mma_kernel<<<ggrid, 512>>>(xs, ws, bo, out);
}